// round 6
// baseline (speedup 1.0000x reference)
#include <cuda_runtime.h>
#include <cstdint>

#define NROWS 131072
#define DIM   192
#define KC    256     // concat(local, global) prototype count
#define MPROT 128
#define INV_T 20.0f   // 1 / 0.05

// ---------------- device scratch (allocation-free: module globals) ----------
__device__ float  g_E[(size_t)NROWS * KC];   // exp(sim/T), 128 MB
__device__ float  g_pnT[DIM * KC];           // normalized protos, transposed [k][j]
__device__ float  g_invx[NROWS];             // per-row 1/||x||
__device__ double g_colsum[3][KC];           // sinkhorn colsum accumulators
__device__ float  g_C[4][KC];                // column factors (C[1..3] used)
__device__ float  g_hgate[MPROT * DIM];      // 0.5 * GLU(globalProto) table
__device__ int    g_lastIdx[MPROT];          // last row assigned per local proto

// ---------------- init: zero accumulators every launch ----------------------
__global__ void k_init() {
    int t = threadIdx.x;
    if (t < MPROT) g_lastIdx[t] = -1;
    for (int i = t; i < 3 * KC; i += blockDim.x)
        ((double*)g_colsum)[i] = 0.0;
}

// ---------------- normalize prototypes, store transposed --------------------
__global__ void k_protos(const float* __restrict__ lp, const float* __restrict__ gp) {
    int j = threadIdx.x;  // 0..255
    const float* src = (j < MPROT) ? (lp + j * DIM) : (gp + (j - MPROT) * DIM);
    float ss = 0.f;
    for (int k = 0; k < DIM; k++) { float v = src[k]; ss += v * v; }
    float inv = rsqrtf(fmaxf(ss, 1e-12f));
    for (int k = 0; k < DIM; k++) g_pnT[k * KC + j] = src[k] * inv;
}

// ---------------- per-row 1/||x|| (warp per row) -----------------------------
__global__ void k_xnorm(const float* __restrict__ x) {
    int w = threadIdx.x >> 5, lane = threadIdx.x & 31;
    int row = blockIdx.x * 8 + w;
    const float* xr = x + (size_t)row * DIM;
    float ss = 0.f;
#pragma unroll
    for (int k = 0; k < 6; k++) { float v = xr[lane + 32 * k]; ss += v * v; }
#pragma unroll
    for (int o = 16; o; o >>= 1) ss += __shfl_xor_sync(0xffffffffu, ss, o);
    if (lane == 0) g_invx[row] = rsqrtf(fmaxf(ss, 1e-12f));
}

// ---------------- GEMM: sim = x @ pnT, E = exp(sim * invx * 20) -------------
// Block: 64 rows x 256 cols, 256 threads. Thread tile 8 rows x 8 cols
// (cols as 4 pairs at 64*j + 2*tx for conflict-free LDS.64 + FFMA2).
// Epilogue ALSO performs sinkhorn iteration 0 (uniform C0 dropped — any
// uniform column scale is argmax-neutral): colsum[0]_j += E_ij / rowsum_i.
__global__ __launch_bounds__(256, 2) void k_gemm(const float* __restrict__ x) {
    __shared__ float As[64][32];
    __shared__ float Bs[32][KC];
    int rowBase = blockIdx.x * 64;
    int tid = threadIdx.x;
    int ty = tid >> 5;   // warp -> 8-row group (lanes share rows => smem broadcast)
    int tx = tid & 31;   // lane -> column pairs

    unsigned long long acc[8][4];
#pragma unroll
    for (int i = 0; i < 8; i++)
#pragma unroll
        for (int j = 0; j < 4; j++) acc[i][j] = 0ull;

    for (int kb = 0; kb < DIM; kb += 32) {
        // A tile 64x32: 512 float4, 2 per thread
#pragma unroll
        for (int u = 0; u < 2; u++) {
            int f = tid + u * 256;
            int r = f >> 3, c = (f & 7) * 4;
            *(float4*)&As[r][c] = *(const float4*)&x[(size_t)(rowBase + r) * DIM + kb + c];
        }
        // B tile 32x256: 2048 float4, 8 per thread (coalesced, conflict-free)
#pragma unroll
        for (int u = 0; u < 8; u++) {
            int f = tid + u * 256;
            int kk = f >> 6, c = (f & 63) * 4;
            *(float4*)&Bs[kk][c] = *(const float4*)&g_pnT[(kb + kk) * KC + c];
        }
        __syncthreads();
#pragma unroll
        for (int k = 0; k < 32; k++) {
            unsigned long long b[4];
#pragma unroll
            for (int j = 0; j < 4; j++)
                b[j] = *(const unsigned long long*)&Bs[k][64 * j + 2 * tx];
#pragma unroll
            for (int i = 0; i < 8; i++) {
                float a = As[ty * 8 + i][k];   // warp-uniform -> broadcast
                unsigned long long a2;
                asm("mov.b64 %0, {%1, %1};" : "=l"(a2) : "f"(a));
#pragma unroll
                for (int j = 0; j < 4; j++)
                    asm("fma.rn.f32x2 %0, %1, %2, %0;"
                        : "+l"(acc[i][j]) : "l"(a2), "l"(b[j]));
            }
        }
        __syncthreads();
    }

    // epilogue: scale by 1/||x||, exponentiate, store E, and accumulate
    // colsum[0]_j += E_ij / rowsum_i (fused sinkhorn iteration 0).
    float colAcc[8] = {0, 0, 0, 0, 0, 0, 0, 0};
#pragma unroll
    for (int i = 0; i < 8; i++) {
        int row = rowBase + ty * 8 + i;
        float inv = g_invx[row];
        float ev[8];
        float rsum = 0.f;
#pragma unroll
        for (int j = 0; j < 4; j++) {
            float lo, hi;
            asm("mov.b64 {%0, %1}, %2;" : "=f"(lo), "=f"(hi) : "l"(acc[i][j]));
            float e0 = expf(INV_T * lo * inv);
            float e1 = expf(INV_T * hi * inv);
            ev[2 * j] = e0; ev[2 * j + 1] = e1;
            rsum += e0 + e1;
            int c = 64 * j + 2 * tx;
            *(float2*)&g_E[(size_t)row * KC + c] = make_float2(e0, e1);
        }
#pragma unroll
        for (int o = 16; o; o >>= 1) rsum += __shfl_xor_sync(0xffffffffu, rsum, o);
        float R = 1.0f / rsum;   // warp holds the full row -> exact rowsum
#pragma unroll
        for (int j = 0; j < 8; j++) colAcc[j] = fmaf(ev[j], R, colAcc[j]);
    }

    // block-reduce colAcc into g_colsum[0] (reuse Bs: mainloop done reading it)
    double (*wsum)[KC] = (double(*)[KC])Bs;
#pragma unroll
    for (int j = 0; j < 4; j++) {
        wsum[ty][64 * j + 2 * tx]     = (double)colAcc[2 * j];
        wsum[ty][64 * j + 2 * tx + 1] = (double)colAcc[2 * j + 1];
    }
    __syncthreads();
    double s = 0.0;
#pragma unroll
    for (int ww = 0; ww < 8; ww++) s += wsum[ww][tid];
    atomicAdd(&g_colsum[0][tid], s);
}

// ---------------- finalize column factors: C[t+1][j] = 1/(256*colsum[t][j]) --
__global__ void k_setC(int t) {
    int j = threadIdx.x;
    g_C[t + 1][j] = (float)(1.0 / (256.0 * g_colsum[t][j]));
}

// ---------------- one sinkhorn iteration: one pass over E --------------------
// R_i = 1/(N * sum_j E_ij C_j);  colsum_j += sum_i E_ij R_i   (double accum)
__global__ __launch_bounds__(256) void k_pass(int iter) {
    __shared__ double wsum[8][KC];
    int tid = threadIdx.x, w = tid >> 5, lane = tid & 31;
    const float* C = g_C[iter];
    float cl[8];
#pragma unroll
    for (int i = 0; i < 8; i++) cl[i] = C[lane * 8 + i];
    float colAcc[8] = {0, 0, 0, 0, 0, 0, 0, 0};
    int row0 = blockIdx.x * 64 + w * 8;
#pragma unroll
    for (int r = 0; r < 8; r++) {
        const float4* p = (const float4*)&g_E[(size_t)(row0 + r) * KC + lane * 8];
        float4 e0 = p[0], e1 = p[1];
        float e[8] = {e0.x, e0.y, e0.z, e0.w, e1.x, e1.y, e1.z, e1.w};
        float rd = 0.f;
#pragma unroll
        for (int i = 0; i < 8; i++) rd = fmaf(e[i], cl[i], rd);
#pragma unroll
        for (int o = 16; o; o >>= 1) rd += __shfl_xor_sync(0xffffffffu, rd, o);
        float R = 1.0f / (131072.0f * rd);
#pragma unroll
        for (int i = 0; i < 8; i++) colAcc[i] = fmaf(e[i], R, colAcc[i]);
    }
#pragma unroll
    for (int i = 0; i < 8; i++) wsum[w][lane * 8 + i] = (double)colAcc[i];
    __syncthreads();
    double s = 0.0;
#pragma unroll
    for (int ww = 0; ww < 8; ww++) s += wsum[ww][tid];
    atomicAdd(&g_colsum[iter][tid], s);
}

// ---------------- 0.5*GLU table for the 128 global prototypes ----------------
__global__ void k_glu(const float* __restrict__ gp, const float* __restrict__ W,
                      const float* __restrict__ bias) {
    __shared__ float gpr[DIM];
    __shared__ float lin[2 * DIM];
    int m = blockIdx.x, t = threadIdx.x;     // 384 threads
    if (t < DIM) gpr[t] = gp[m * DIM + t];
    __syncthreads();
    float s = bias[t];
    for (int k = 0; k < DIM; k++) s = fmaf(gpr[k], W[(size_t)k * 2 * DIM + t], s);
    lin[t] = s;
    __syncthreads();
    if (t < DIM)
        g_hgate[m * DIM + t] = 0.5f * lin[t] / (1.0f + expf(-lin[t + DIM]));
}

// ---------------- argmax + fused output (warp per row) -----------------------
__global__ __launch_bounds__(256) void k_out(const float* __restrict__ x,
                                             float* __restrict__ out) {
    int tid = threadIdx.x, w = tid >> 5, lane = tid & 31;
    float cl[8];
#pragma unroll
    for (int i = 0; i < 8; i++) cl[i] = g_C[3][lane * 8 + i];
    int row0 = blockIdx.x * 64 + w * 8;
    for (int r = 0; r < 8; r++) {
        int row = row0 + r;
        const float4* p = (const float4*)&g_E[(size_t)row * KC + lane * 8];
        float4 e0 = p[0], e1 = p[1];
        float e[8] = {e0.x, e0.y, e0.z, e0.w, e1.x, e1.y, e1.z, e1.w};
        // lanes 0-15 cover cols 0..127 (local), 16-31 cover 128..255 (global)
        float best = -1.0f; int bi = lane * 8;
#pragma unroll
        for (int i = 0; i < 8; i++) {
            float v = e[i] * cl[i];
            if (v > best) { best = v; bi = lane * 8 + i; }   // first-max wins
        }
#pragma unroll
        for (int o = 8; o; o >>= 1) {  // butterfly within each 16-lane half
            float ov = __shfl_xor_sync(0xffffffffu, best, o);
            int   oi = __shfl_xor_sync(0xffffffffu, bi, o);
            if (ov > best || (ov == best && oi < bi)) { best = ov; bi = oi; }
        }
        int la = __shfl_sync(0xffffffffu, bi, 0);
        int ga = __shfl_sync(0xffffffffu, bi, 16) - MPROT;
        if (lane == 0) atomicMax(&g_lastIdx[la], row);

        const float* hg = g_hgate + (size_t)ga * DIM;
        const float* xr = x + (size_t)row * DIM;
        float o6[6]; float ss = 0.f;
#pragma unroll
        for (int k = 0; k < 6; k++) {
            int c = lane + 32 * k;
            float v = hg[c] + 0.5f * xr[c];
            o6[k] = v; ss += v * v;
        }
#pragma unroll
        for (int o = 16; o; o >>= 1) ss += __shfl_xor_sync(0xffffffffu, ss, o);
        float inv = rsqrtf(fmaxf(ss, 1e-12f));
        float* orow = out + (size_t)row * DIM;
#pragma unroll
        for (int k = 0; k < 6; k++) orow[lane + 32 * k] = o6[k] * inv;
    }
}

// ---------------- EMA-updated local prototypes (last-write-wins) -------------
__global__ void k_newlocal(const float* __restrict__ lp, const float* __restrict__ x,
                           float* __restrict__ out) {
    int e = blockIdx.x * 256 + threadIdx.x;   // 24576 elements
    int m = e / DIM, d = e % DIM;
    int i = g_lastIdx[m];
    float v = (i < 0) ? lp[e] : 0.96f * lp[e] + 0.04f * x[(size_t)i * DIM + d];
    out[(size_t)NROWS * DIM + e] = v;
}

// ---------------- launch ------------------------------------------------------
extern "C" void kernel_launch(void* const* d_in, const int* in_sizes, int n_in,
                              void* d_out, int out_size) {
    const float* x  = (const float*)d_in[0];  // projections [128,1024,192]
    const float* lp = (const float*)d_in[1];  // localPrototypes [128,192]
    const float* gp = (const float*)d_in[2];  // globalPrototypes [128,192]
    const float* W  = (const float*)d_in[3];  // glu_W [192,384]
    const float* b  = (const float*)d_in[4];  // glu_b [384]
    float* out = (float*)d_out;               // [normed | new_local]

    k_init<<<1, 256>>>();
    k_protos<<<1, 256>>>(lp, gp);
    k_xnorm<<<NROWS / 8, 256>>>(x);
    k_gemm<<<NROWS / 64, 256>>>(x);  // also produces colsum[0] (fused iter 0)
    k_setC<<<1, 256>>>(0);           // C1
    k_pass<<<NROWS / 64, 256>>>(1);  // -> colsum[1]
    k_setC<<<1, 256>>>(1);           // C2
    k_pass<<<NROWS / 64, 256>>>(2);  // -> colsum[2]
    k_setC<<<1, 256>>>(2);           // C3
    k_glu<<<MPROT, 2 * DIM>>>(gp, W, b);
    k_out<<<NROWS / 64, 256>>>(x, out);
    k_newlocal<<<MPROT * DIM / 256, 256>>>(lp, x, out);
}